// round 11
// baseline (speedup 1.0000x reference)
#include <cuda_runtime.h>

#define N_NODES 100000
#define N_EDGES 1600000
#define F_INP   8
#define H       128
#define NLAYERS 4
#define E_FEAT  16
#define NG      256
#define OUT_F   256

#define SCAN_CHUNK 512
#define SCAN_NBLK  196   // 196*512 = 100352 >= N_NODES
#define WE 64            // edges per window (2 warps per window)

typedef unsigned long long u64;

// ---------------- scratch (device globals; allocations forbidden) ----------------
__device__ __align__(16) float g_h   [(size_t)N_NODES * H];
__device__ __align__(16) float g_agg [(size_t)N_NODES * H];   // seeded with h, gather adds
__device__ __align__(16) float g_hc  [(size_t)N_NODES * H];
__device__ __align__(16) float g_stats[2 * H];
__device__ __align__(16) float g_bn   [2 * H];
__device__ __align__(16) float g_hp  [NG * H];
__device__ float g_cntg[NG];

__device__ __align__(16) int g_cnt_i [N_NODES];   // degree; self-cleaned by k_fill
__device__ int g_rowptr[N_NODES + 1];
__device__ int g_cursor[N_NODES];
__device__ __align__(8) int2 g_sd[N_EDGES];       // (src, dst) in CSR order
// attr in CSR order, each value duplicated as (a,a) for direct f32x2 FMA
__device__ __align__(16) u64 g_attrs2[(size_t)N_EDGES * E_FEAT];

// ---------------- f32x2 helpers ----------------
__device__ __forceinline__ u64 pk2(float x, float y) {
    u64 r; asm("mov.b64 %0,{%1,%2};" : "=l"(r) : "f"(x), "f"(y)); return r;
}
__device__ __forceinline__ void up2(u64 p, float& x, float& y) {
    asm("mov.b64 {%0,%1},%2;" : "=f"(x), "=f"(y) : "l"(p));
}
__device__ __forceinline__ u64 fma2(u64 a, u64 b, u64 c) {
    u64 d; asm("fma.rn.f32x2 %0,%1,%2,%3;" : "=l"(d) : "l"(a), "l"(b), "l"(c)); return d;
}
__device__ __forceinline__ u64 add2(u64 a, u64 b) {
    u64 d; asm("add.rn.f32x2 %0,%1,%2;" : "=l"(d) : "l"(a), "l"(b)); return d;
}
__device__ __forceinline__ void flush2(int d, int fo, u64 v) {
    float x, y; up2(v, x, y);
    float* p = g_agg + (size_t)d * H + fo;
    asm volatile("red.global.add.v2.f32 [%0], {%1,%2};"
                 :: "l"(p), "f"(x), "f"(y) : "memory");
}

// ================= my launch 0: embed (h AND agg seed) + degree hist + zero =================
#define MEGA_EMBED_BLKS  N_NODES
#define MEGA_HIST_BLKS   ((N_EDGES + 127) / 128)
#define MEGA_ZERO_BLKS   ((NG * H + 127) / 128)
__global__ void k_megainit(const float* __restrict__ x,
                           const float* __restrict__ W,
                           const float* __restrict__ b,
                           const int* __restrict__ ei) {
    int blk = blockIdx.x;
    int t = threadIdx.x;
    if (blk < MEGA_EMBED_BLKS) {
        const float* xr = x + (size_t)blk * F_INP;
        float acc = b[t];
#pragma unroll
        for (int k = 0; k < F_INP; k++)
            acc = fmaf(xr[k], W[k * H + t], acc);
        g_h  [(size_t)blk * H + t] = acc;
        g_agg[(size_t)blk * H + t] = acc;    // seed for layer-0 gather flushes
        return;
    }
    blk -= MEGA_EMBED_BLKS;
    if (blk < MEGA_HIST_BLKS) {
        int e = blk * 128 + t;
        if (e < N_EDGES) atomicAdd(&g_cnt_i[ei[N_EDGES + e]], 1);
        return;
    }
    blk -= MEGA_HIST_BLKS;
    int i = blk * 128 + t;
    if (i < NG * H) g_hp[i] = 0.f;
    if (i < NG)     g_cntg[i] = 0.f;
}

// ================= my launch 1: fused exclusive scan -> rowptr, cursor =================
__global__ void __launch_bounds__(SCAN_CHUNK) k_scanfused() {
    __shared__ int s[SCAN_CHUNK];
    __shared__ int sb[SCAN_CHUNK];
    int t = threadIdx.x;
    int lim = blockIdx.x * SCAN_CHUNK;

    int acc = 0;
    const int4* c4 = (const int4*)g_cnt_i;
    for (int i4 = t; i4 < lim / 4; i4 += SCAN_CHUNK) {
        int4 v = c4[i4];
        acc += v.x + v.y + v.z + v.w;
    }
    sb[t] = acc; __syncthreads();
    for (int o = SCAN_CHUNK / 2; o > 0; o >>= 1) {
        if (t < o) sb[t] += sb[t + o];
        __syncthreads();
    }
    int base = sb[0];

    int i = lim + t;
    int v = (i < N_NODES) ? g_cnt_i[i] : 0;
    s[t] = v; __syncthreads();
    for (int o = 1; o < SCAN_CHUNK; o <<= 1) {
        int tv = (t >= o) ? s[t - o] : 0;
        __syncthreads();
        s[t] += tv;
        __syncthreads();
    }
    if (i < N_NODES) {
        int ex = base + s[t] - v;
        g_rowptr[i] = ex;
        g_cursor[i] = ex;
        if (i == N_NODES - 1) g_rowptr[N_NODES] = base + s[t];
    }
}

// ================= my launch 2: fill CSR directly (src/dst + dup-packed attr) =================
__global__ void k_fill(const int* __restrict__ ei, const float* __restrict__ attr) {
    int e = blockIdx.x * blockDim.x + threadIdx.x;
    if (e < N_NODES) g_cnt_i[e] = 0;      // dead after scan; self-clean for replay
    if (e >= N_EDGES) return;
    int d = ei[N_EDGES + e];
    int pos = atomicAdd(&g_cursor[d], 1);
    g_sd[pos] = make_int2(ei[e], d);
    const float4* ar = (const float4*)(attr + (size_t)e * E_FEAT);
    u64* aw = g_attrs2 + (size_t)pos * E_FEAT;
#pragma unroll
    for (int q = 0; q < 4; q++) {
        float4 a = ar[q];
        aw[q * 4 + 0] = pk2(a.x, a.x);
        aw[q * 4 + 1] = pk2(a.y, a.y);
        aw[q * 4 + 2] = pk2(a.z, a.z);
        aw[q * 4 + 3] = pk2(a.w, a.w);
    }
}

// ================= gather+aggregate, feature-split over warp pairs =================
// Window = WE consecutive CSR edges, processed by 2 warps; each warp owns 64
// features (lane owns 2 -> weight slice in 16 u64 regs). Accumulate relu(h+e)
// in an f32x2; flush per-dst partial sums via red.global.add.v2 into g_agg
// (pre-seeded with h).
__global__ void __launch_bounds__(256) k_gatheragg(const float* __restrict__ W,
                                                   const float* __restrict__ b) {
    int tid  = threadIdx.x;
    int lane = tid & 31;
    int warp = tid >> 5;                       // 0..7
    int win  = blockIdx.x * 4 + (warp >> 1);   // 4 windows per block
    int e0 = win * WE;
    if (e0 >= N_EDGES) return;
    int e1 = e0 + WE;
    if (e1 > N_EDGES) e1 = N_EDGES;
    int fo = (warp & 1) * 64 + lane * 2;       // this thread's 2 features

    u64 wk[E_FEAT];
#pragma unroll
    for (int k = 0; k < E_FEAT; k++)
        wk[k] = *(const u64*)(W + k * H + fo);
    u64 bb = *(const u64*)(b + fo);

    u64 acc = 0;                               // (0.f, 0.f)
    int2 sd = g_sd[e0];
    int dcur = sd.y;
    u64 hs = *(const u64*)(g_h + (size_t)sd.x * H + fo);

    for (int e = e0; e < e1; e++) {
        bool more = (e + 1 < e1);
        int2 sdn = more ? g_sd[e + 1] : make_int2(0, dcur);
        u64 hn = hs;
        if (more) hn = *(const u64*)(g_h + (size_t)sdn.x * H + fo);

        const ulonglong2* ap = (const ulonglong2*)(g_attrs2 + (size_t)e * E_FEAT);
        u64 p = bb;
#pragma unroll
        for (int k2 = 0; k2 < E_FEAT / 2; k2++) {
            ulonglong2 aa = ap[k2];
            p = fma2(aa.x, wk[2 * k2],     p);
            p = fma2(aa.y, wk[2 * k2 + 1], p);
        }
        float m0, m1, h0, h1;
        up2(p, m0, m1); up2(hs, h0, h1);
        float r0 = fmaxf(h0 + m0, 0.f);
        float r1 = fmaxf(h1 + m1, 0.f);
        acc = add2(acc, pk2(r0, r1));

        if (sdn.y != dcur) {                   // next edge starts a new dst
            flush2(dcur, fo, acc);
            acc = 0;
        }
        dcur = sdn.y;
        hs = hn;
    }
    flush2(dcur, fo, acc);
}

// ================= node GEMM: hc = agg @ nn_W + nn_b ; BN sum/sumsq =================
__global__ void __launch_bounds__(256) k_nodegemm(const float* __restrict__ W,
                                                  const float* __restrict__ b) {
    extern __shared__ float sW[];   // 64KB
    for (int idx = threadIdx.x; idx < H * H / 4; idx += blockDim.x)
        ((float4*)sW)[idx] = ((const float4*)W)[idx];
    __syncthreads();

    int lane = threadIdx.x & 31;
    int wid  = (blockIdx.x * blockDim.x + threadIdx.x) >> 5;
    int nw   = (gridDim.x * blockDim.x) >> 5;
    float4 bb = *(const float4*)(b + lane * 4);
    u64 bias01 = pk2(bb.x, bb.y), bias23 = pk2(bb.z, bb.w);

    float4 sum = make_float4(0, 0, 0, 0);
    float4 sq  = make_float4(0, 0, 0, 0);

    for (int i0 = wid * 8; i0 < N_NODES; i0 += nw * 8) {
        u64 acc01[8], acc23[8];
#pragma unroll
        for (int n = 0; n < 8; n++) { acc01[n] = bias01; acc23[n] = bias23; }

#pragma unroll 4
        for (int k4 = 0; k4 < H; k4 += 4) {
            float4 av[8];
#pragma unroll
            for (int n = 0; n < 8; n++)
                av[n] = *(const float4*)(g_agg + (size_t)(i0 + n) * H + k4);
#pragma unroll
            for (int kk = 0; kk < 4; kk++) {
                ulonglong2 wp = *(const ulonglong2*)(sW + (k4 + kk) * H + lane * 4);
#pragma unroll
                for (int n = 0; n < 8; n++) {
                    float a = (kk == 0) ? av[n].x : (kk == 1) ? av[n].y
                             : (kk == 2) ? av[n].z : av[n].w;
                    u64 ap = pk2(a, a);
                    acc01[n] = fma2(ap, wp.x, acc01[n]);
                    acc23[n] = fma2(ap, wp.y, acc23[n]);
                }
            }
        }
#pragma unroll
        for (int n = 0; n < 8; n++) {
            float x0, x1, x2, x3;
            up2(acc01[n], x0, x1); up2(acc23[n], x2, x3);
            *(float4*)(g_hc + (size_t)(i0 + n) * H + lane * 4) =
                make_float4(x0, x1, x2, x3);
            sum.x += x0; sum.y += x1; sum.z += x2; sum.w += x3;
            sq.x += x0 * x0; sq.y += x1 * x1; sq.z += x2 * x2; sq.w += x3 * x3;
        }
    }
    int f = lane * 4;
    atomicAdd(&g_stats[f + 0], sum.x);
    atomicAdd(&g_stats[f + 1], sum.y);
    atomicAdd(&g_stats[f + 2], sum.z);
    atomicAdd(&g_stats[f + 3], sum.w);
    atomicAdd(&g_stats[H + f + 0], sq.x);
    atomicAdd(&g_stats[H + f + 1], sq.y);
    atomicAdd(&g_stats[H + f + 2], sq.z);
    atomicAdd(&g_stats[H + f + 3], sq.w);
}

__global__ void k_bnstats() {
    int j = threadIdx.x;
    float s = g_stats[j];
    float q = g_stats[H + j];
    const float inv = 1.0f / (float)N_NODES;
    float mu  = s * inv;
    float var = q * inv - mu * mu;
    g_bn[j]     = mu;
    g_bn[H + j] = rsqrtf(var + 1e-5f);
    g_stats[j] = 0.f;
    g_stats[H + j] = 0.f;
}

// apply BN + exact GELU + residual; writes h AND re-seeds agg for next layer
__global__ void k_apply(const float* __restrict__ gam,
                        const float* __restrict__ bet) {
    int idx = blockIdx.x * blockDim.x + threadIdx.x;
    const int total = N_NODES * H / 4;
    if (idx >= total) return;
    int f = (idx & (H / 4 - 1)) * 4;
    float4 hc  = ((const float4*)g_hc)[idx];
    float4 hv  = ((float4*)g_h)[idx];
    float4 mu4 = *(const float4*)(g_bn + f);
    float4 rs4 = *(const float4*)(g_bn + H + f);
    float4 gg  = *(const float4*)(gam + f);
    float4 bb  = *(const float4*)(bet + f);

    float x0 = (hc.x - mu4.x) * rs4.x * gg.x + bb.x;
    float x1 = (hc.y - mu4.y) * rs4.y * gg.y + bb.y;
    float x2 = (hc.z - mu4.z) * rs4.z * gg.z + bb.z;
    float x3 = (hc.w - mu4.w) * rs4.w * gg.w + bb.w;
    hv.x += x0 * normcdff(x0);
    hv.y += x1 * normcdff(x1);
    hv.z += x2 * normcdff(x2);
    hv.w += x3 * normcdff(x3);
    ((float4*)g_h)[idx]   = hv;
    ((float4*)g_agg)[idx] = hv;      // seed for next layer's gather flushes
}

__global__ void k_pool(const int* __restrict__ batch) {
    int j = threadIdx.x;
    int chunk = (N_NODES + gridDim.x - 1) / gridDim.x;
    int i0 = blockIdx.x * chunk;
    int i1 = min(N_NODES, i0 + chunk);
    if (i0 >= i1) return;
    int curG = batch[i0];
    float acc = 0.f;
    int run = 0;
    for (int i = i0; i < i1; i++) {
        int g = batch[i];
        float v = g_h[(size_t)i * H + j];
        if (g != curG) {
            atomicAdd(&g_hp[curG * H + j], acc);
            if (j == 0) atomicAdd(&g_cntg[curG], (float)run);
            acc = 0.f; run = 0; curG = g;
        }
        acc += v; run++;
    }
    atomicAdd(&g_hp[curG * H + j], acc);
    if (j == 0) atomicAdd(&g_cntg[curG], (float)run);
}

__global__ void k_out(const float* __restrict__ W,
                      const float* __restrict__ b,
                      float* __restrict__ out) {
    int g = blockIdx.x;
    int j = threadIdx.x;
    const float* hp = g_hp + g * H;
    float acc = g_cntg[g] * b[j];
#pragma unroll 8
    for (int k = 0; k < H; k++)
        acc = fmaf(hp[k], W[k * OUT_F + j], acc);
    out[g * OUT_F + j] = acc;
}

extern "C" void kernel_launch(void* const* d_in, const int* in_sizes, int n_in,
                              void* d_out, int out_size) {
    const float* x      = (const float*)d_in[0];
    const int*   ei     = (const int*)  d_in[1];
    const float* attr   = (const float*)d_in[2];
    const int*   batch  = (const int*)  d_in[3];
    const float* emb_W  = (const float*)d_in[4];
    const float* emb_b  = (const float*)d_in[5];
    const float* edge_W = (const float*)d_in[6];
    const float* edge_b = (const float*)d_in[7];
    const float* nn_W   = (const float*)d_in[8];
    const float* nn_b   = (const float*)d_in[9];
    const float* bn_g   = (const float*)d_in[10];
    const float* bn_b   = (const float*)d_in[11];
    const float* lin_W  = (const float*)d_in[12];
    const float* lin_b  = (const float*)d_in[13];
    float* out = (float*)d_out;

    cudaFuncSetAttribute(k_nodegemm,
                         cudaFuncAttributeMaxDynamicSharedMemorySize,
                         H * H * (int)sizeof(float));

    const int ew_grid = (N_NODES * H / 4 + 255) / 256;
    const int eg      = (N_EDGES + 255) / 256;
    const int mega    = MEGA_EMBED_BLKS + MEGA_HIST_BLKS + MEGA_ZERO_BLKS;
    const int nwin    = (N_EDGES + WE - 1) / WE;          // 25000 windows
    const int ggrid   = (nwin + 3) / 4;                   // 4 windows (8 warps) per block

    k_megainit<<<mega, 128>>>(x, emb_W, emb_b, ei);      // my launch 0
    k_scanfused<<<SCAN_NBLK, SCAN_CHUNK>>>();             // 1
    k_fill<<<eg, 256>>>(ei, attr);                        // 2
    for (int l = 0; l < NLAYERS; l++) {
        k_gatheragg<<<ggrid, 256>>>(                      // 3 -> ncu global #5
            edge_W + (size_t)l * E_FEAT * H, edge_b + (size_t)l * H);
        k_nodegemm<<<296, 256, H * H * sizeof(float)>>>(
            nn_W + (size_t)l * H * H, nn_b + (size_t)l * H);
        k_bnstats<<<1, H>>>();
        k_apply<<<ew_grid, 256>>>(bn_g + (size_t)l * H, bn_b + (size_t)l * H);
    }
    k_pool<<<1024, 128>>>(batch);
    k_out<<<NG, OUT_F>>>(lin_W, lin_b, out);
}

// round 12
// speedup vs baseline: 1.9582x; 1.9582x over previous
#include <cuda_runtime.h>

#define N_NODES 100000
#define N_EDGES 1600000
#define F_INP   8
#define H       128
#define NLAYERS 4
#define E_FEAT  16
#define NG      256
#define OUT_F   256

#define SCAN_CHUNK 512
#define SCAN_NBLK  196   // 196*512 = 100352 >= N_NODES
#define CHUNK 256        // edges per block (exactly divides N_EDGES)
#define WE 64            // edges per warp-pair window

typedef unsigned long long u64;

// ---------------- scratch (device globals; allocations forbidden) ----------------
__device__ __align__(16) float g_h   [(size_t)N_NODES * H];
__device__ __align__(16) float g_agg [(size_t)N_NODES * H];   // seeded with h, gather adds
__device__ __align__(16) float g_hc  [(size_t)N_NODES * H];
__device__ __align__(16) float g_stats[2 * H];
__device__ __align__(16) float g_bn   [2 * H];
__device__ __align__(16) float g_hp  [NG * H];
__device__ float g_cntg[NG];

__device__ __align__(16) int g_cnt_i [N_NODES];   // degree; self-cleaned by k_fill
__device__ int g_rowptr[N_NODES + 1];
__device__ int g_cursor[N_NODES];
__device__ __align__(8) int2 g_sd[N_EDGES];       // (src, dst) in CSR order
// attr in CSR order, each value duplicated as (a,a) for direct f32x2 FMA
__device__ __align__(16) u64 g_attrs2[(size_t)N_EDGES * E_FEAT];

// ---------------- f32x2 helpers ----------------
__device__ __forceinline__ u64 pk2(float x, float y) {
    u64 r; asm("mov.b64 %0,{%1,%2};" : "=l"(r) : "f"(x), "f"(y)); return r;
}
__device__ __forceinline__ void up2(u64 p, float& x, float& y) {
    asm("mov.b64 {%0,%1},%2;" : "=f"(x), "=f"(y) : "l"(p));
}
__device__ __forceinline__ u64 fma2(u64 a, u64 b, u64 c) {
    u64 d; asm("fma.rn.f32x2 %0,%1,%2,%3;" : "=l"(d) : "l"(a), "l"(b), "l"(c)); return d;
}
__device__ __forceinline__ u64 add2(u64 a, u64 b) {
    u64 d; asm("add.rn.f32x2 %0,%1,%2;" : "=l"(d) : "l"(a), "l"(b)); return d;
}
__device__ __forceinline__ void flush2(int d, int fo, u64 v) {
    float x, y; up2(v, x, y);
    float* p = g_agg + (size_t)d * H + fo;
    asm volatile("red.global.add.v2.f32 [%0], {%1,%2};"
                 :: "l"(p), "f"(x), "f"(y) : "memory");
}

// ================= my launch 0: embed (h AND agg seed) + degree hist + zero =================
#define MEGA_EMBED_BLKS  N_NODES
#define MEGA_HIST_BLKS   ((N_EDGES + 127) / 128)
#define MEGA_ZERO_BLKS   ((NG * H + 127) / 128)
__global__ void k_megainit(const float* __restrict__ x,
                           const float* __restrict__ W,
                           const float* __restrict__ b,
                           const int* __restrict__ ei) {
    int blk = blockIdx.x;
    int t = threadIdx.x;
    if (blk < MEGA_EMBED_BLKS) {
        const float* xr = x + (size_t)blk * F_INP;
        float acc = b[t];
#pragma unroll
        for (int k = 0; k < F_INP; k++)
            acc = fmaf(xr[k], W[k * H + t], acc);
        g_h  [(size_t)blk * H + t] = acc;
        g_agg[(size_t)blk * H + t] = acc;    // seed for layer-0 gather flushes
        return;
    }
    blk -= MEGA_EMBED_BLKS;
    if (blk < MEGA_HIST_BLKS) {
        int e = blk * 128 + t;
        if (e < N_EDGES) atomicAdd(&g_cnt_i[ei[N_EDGES + e]], 1);
        return;
    }
    blk -= MEGA_HIST_BLKS;
    int i = blk * 128 + t;
    if (i < NG * H) g_hp[i] = 0.f;
    if (i < NG)     g_cntg[i] = 0.f;
}

// ================= my launch 1: fused exclusive scan -> rowptr, cursor =================
__global__ void __launch_bounds__(SCAN_CHUNK) k_scanfused() {
    __shared__ int s[SCAN_CHUNK];
    __shared__ int sb[SCAN_CHUNK];
    int t = threadIdx.x;
    int lim = blockIdx.x * SCAN_CHUNK;

    int acc = 0;
    const int4* c4 = (const int4*)g_cnt_i;
    for (int i4 = t; i4 < lim / 4; i4 += SCAN_CHUNK) {
        int4 v = c4[i4];
        acc += v.x + v.y + v.z + v.w;
    }
    sb[t] = acc; __syncthreads();
    for (int o = SCAN_CHUNK / 2; o > 0; o >>= 1) {
        if (t < o) sb[t] += sb[t + o];
        __syncthreads();
    }
    int base = sb[0];

    int i = lim + t;
    int v = (i < N_NODES) ? g_cnt_i[i] : 0;
    s[t] = v; __syncthreads();
    for (int o = 1; o < SCAN_CHUNK; o <<= 1) {
        int tv = (t >= o) ? s[t - o] : 0;
        __syncthreads();
        s[t] += tv;
        __syncthreads();
    }
    if (i < N_NODES) {
        int ex = base + s[t] - v;
        g_rowptr[i] = ex;
        g_cursor[i] = ex;
        if (i == N_NODES - 1) g_rowptr[N_NODES] = base + s[t];
    }
}

// ================= my launch 2: fill CSR directly (src/dst + dup-packed attr) =================
__global__ void k_fill(const int* __restrict__ ei, const float* __restrict__ attr) {
    int e = blockIdx.x * blockDim.x + threadIdx.x;
    if (e < N_NODES) g_cnt_i[e] = 0;      // dead after scan; self-clean for replay
    if (e >= N_EDGES) return;
    int d = ei[N_EDGES + e];
    int pos = atomicAdd(&g_cursor[d], 1);
    g_sd[pos] = make_int2(ei[e], d);
    const float4* ar = (const float4*)(attr + (size_t)e * E_FEAT);
    u64* aw = g_attrs2 + (size_t)pos * E_FEAT;
#pragma unroll
    for (int q = 0; q < 4; q++) {
        float4 a = ar[q];
        aw[q * 4 + 0] = pk2(a.x, a.x);
        aw[q * 4 + 1] = pk2(a.y, a.y);
        aw[q * 4 + 2] = pk2(a.z, a.z);
        aw[q * 4 + 3] = pk2(a.w, a.w);
    }
}

// ================= gather+aggregate: smem-staged attrs + feature-split warp pairs ======
// Block = 256-edge CSR chunk. Cooperative coalesced load of dup-packed attrs
// (32KB) + (src,dst) (2KB) into smem; then 4 warp-pairs each process a 64-edge
// window, each warp owning 64 features (weight slice = 16 u64 regs). attr reads
// are LDS broadcasts (single shared copy); h gather is coalesced LDG.64 with
// depth-1 prefetch; per-dst partials flushed via red.global.add.v2 into g_agg.
__global__ void __launch_bounds__(256) k_gatheragg(const float* __restrict__ W,
                                                   const float* __restrict__ b) {
    __shared__ __align__(16) u64  sA[CHUNK * E_FEAT];   // 32KB
    __shared__ __align__(8)  int2 sSD[CHUNK];           // 2KB

    int tid = threadIdx.x;
    size_t ebase = (size_t)blockIdx.x * CHUNK;

    // cooperative staging: 2048 ulonglong2 = 8 per thread, fully coalesced
    {
        const ulonglong2* gsrc = (const ulonglong2*)(g_attrs2 + ebase * E_FEAT);
        ulonglong2* sdst = (ulonglong2*)sA;
#pragma unroll
        for (int i = 0; i < (CHUNK * E_FEAT / 2) / 256; i++)
            sdst[tid + 256 * i] = gsrc[tid + 256 * i];
        sSD[tid] = g_sd[ebase + tid];
    }
    __syncthreads();

    int lane = tid & 31;
    int warp = tid >> 5;                    // 0..7
    int wstart = (warp >> 1) * WE;          // local window start
    int fo = (warp & 1) * 64 + lane * 2;    // this thread's 2 features

    u64 wk[E_FEAT];
#pragma unroll
    for (int k = 0; k < E_FEAT; k++)
        wk[k] = *(const u64*)(W + k * H + fo);
    u64 bb = *(const u64*)(b + fo);

    u64 acc = 0;                            // (0,0)
    int2 sd = sSD[wstart];
    int dcur = sd.y;
    u64 hs = *(const u64*)(g_h + (size_t)sd.x * H + fo);

#pragma unroll 2
    for (int le = wstart; le < wstart + WE; le++) {
        bool more = (le + 1 < wstart + WE);
        int2 sdn = more ? sSD[le + 1] : make_int2(0, dcur);
        u64 hn = hs;
        if (more) hn = *(const u64*)(g_h + (size_t)sdn.x * H + fo);

        const ulonglong2* ap = (const ulonglong2*)(sA + le * E_FEAT);
        u64 p = bb, q = 0;                  // two 8-deep chains
#pragma unroll
        for (int k2 = 0; k2 < 4; k2++) {
            ulonglong2 aa = ap[k2];
            p = fma2(aa.x, wk[2 * k2],     p);
            p = fma2(aa.y, wk[2 * k2 + 1], p);
        }
#pragma unroll
        for (int k2 = 4; k2 < 8; k2++) {
            ulonglong2 aa = ap[k2];
            q = fma2(aa.x, wk[2 * k2],     q);
            q = fma2(aa.y, wk[2 * k2 + 1], q);
        }
        p = add2(p, q);
        float m0, m1, h0, h1;
        up2(p, m0, m1); up2(hs, h0, h1);
        acc = add2(acc, pk2(fmaxf(h0 + m0, 0.f), fmaxf(h1 + m1, 0.f)));

        if (sdn.y != dcur) {                // next edge starts a new dst
            flush2(dcur, fo, acc);
            acc = 0;
        }
        dcur = sdn.y;
        hs = hn;
    }
    flush2(dcur, fo, acc);
}

// ================= node GEMM: hc = agg @ nn_W + nn_b ; BN sum/sumsq =================
__global__ void __launch_bounds__(256) k_nodegemm(const float* __restrict__ W,
                                                  const float* __restrict__ b) {
    extern __shared__ float sW[];   // 64KB
    for (int idx = threadIdx.x; idx < H * H / 4; idx += blockDim.x)
        ((float4*)sW)[idx] = ((const float4*)W)[idx];
    __syncthreads();

    int lane = threadIdx.x & 31;
    int wid  = (blockIdx.x * blockDim.x + threadIdx.x) >> 5;
    int nw   = (gridDim.x * blockDim.x) >> 5;
    float4 bb = *(const float4*)(b + lane * 4);
    u64 bias01 = pk2(bb.x, bb.y), bias23 = pk2(bb.z, bb.w);

    float4 sum = make_float4(0, 0, 0, 0);
    float4 sq  = make_float4(0, 0, 0, 0);

    for (int i0 = wid * 8; i0 < N_NODES; i0 += nw * 8) {
        u64 acc01[8], acc23[8];
#pragma unroll
        for (int n = 0; n < 8; n++) { acc01[n] = bias01; acc23[n] = bias23; }

#pragma unroll 4
        for (int k4 = 0; k4 < H; k4 += 4) {
            float4 av[8];
#pragma unroll
            for (int n = 0; n < 8; n++)
                av[n] = *(const float4*)(g_agg + (size_t)(i0 + n) * H + k4);
#pragma unroll
            for (int kk = 0; kk < 4; kk++) {
                ulonglong2 wp = *(const ulonglong2*)(sW + (k4 + kk) * H + lane * 4);
#pragma unroll
                for (int n = 0; n < 8; n++) {
                    float a = (kk == 0) ? av[n].x : (kk == 1) ? av[n].y
                             : (kk == 2) ? av[n].z : av[n].w;
                    u64 ap = pk2(a, a);
                    acc01[n] = fma2(ap, wp.x, acc01[n]);
                    acc23[n] = fma2(ap, wp.y, acc23[n]);
                }
            }
        }
#pragma unroll
        for (int n = 0; n < 8; n++) {
            float x0, x1, x2, x3;
            up2(acc01[n], x0, x1); up2(acc23[n], x2, x3);
            *(float4*)(g_hc + (size_t)(i0 + n) * H + lane * 4) =
                make_float4(x0, x1, x2, x3);
            sum.x += x0; sum.y += x1; sum.z += x2; sum.w += x3;
            sq.x += x0 * x0; sq.y += x1 * x1; sq.z += x2 * x2; sq.w += x3 * x3;
        }
    }
    int f = lane * 4;
    atomicAdd(&g_stats[f + 0], sum.x);
    atomicAdd(&g_stats[f + 1], sum.y);
    atomicAdd(&g_stats[f + 2], sum.z);
    atomicAdd(&g_stats[f + 3], sum.w);
    atomicAdd(&g_stats[H + f + 0], sq.x);
    atomicAdd(&g_stats[H + f + 1], sq.y);
    atomicAdd(&g_stats[H + f + 2], sq.z);
    atomicAdd(&g_stats[H + f + 3], sq.w);
}

__global__ void k_bnstats() {
    int j = threadIdx.x;
    float s = g_stats[j];
    float q = g_stats[H + j];
    const float inv = 1.0f / (float)N_NODES;
    float mu  = s * inv;
    float var = q * inv - mu * mu;
    g_bn[j]     = mu;
    g_bn[H + j] = rsqrtf(var + 1e-5f);
    g_stats[j] = 0.f;
    g_stats[H + j] = 0.f;
}

// apply BN + exact GELU + residual; writes h AND re-seeds agg for next layer
__global__ void k_apply(const float* __restrict__ gam,
                        const float* __restrict__ bet) {
    int idx = blockIdx.x * blockDim.x + threadIdx.x;
    const int total = N_NODES * H / 4;
    if (idx >= total) return;
    int f = (idx & (H / 4 - 1)) * 4;
    float4 hc  = ((const float4*)g_hc)[idx];
    float4 hv  = ((float4*)g_h)[idx];
    float4 mu4 = *(const float4*)(g_bn + f);
    float4 rs4 = *(const float4*)(g_bn + H + f);
    float4 gg  = *(const float4*)(gam + f);
    float4 bb  = *(const float4*)(bet + f);

    float x0 = (hc.x - mu4.x) * rs4.x * gg.x + bb.x;
    float x1 = (hc.y - mu4.y) * rs4.y * gg.y + bb.y;
    float x2 = (hc.z - mu4.z) * rs4.z * gg.z + bb.z;
    float x3 = (hc.w - mu4.w) * rs4.w * gg.w + bb.w;
    hv.x += x0 * normcdff(x0);
    hv.y += x1 * normcdff(x1);
    hv.z += x2 * normcdff(x2);
    hv.w += x3 * normcdff(x3);
    ((float4*)g_h)[idx]   = hv;
    ((float4*)g_agg)[idx] = hv;      // seed for next layer's gather flushes
}

__global__ void k_pool(const int* __restrict__ batch) {
    int j = threadIdx.x;
    int chunk = (N_NODES + gridDim.x - 1) / gridDim.x;
    int i0 = blockIdx.x * chunk;
    int i1 = min(N_NODES, i0 + chunk);
    if (i0 >= i1) return;
    int curG = batch[i0];
    float acc = 0.f;
    int run = 0;
    for (int i = i0; i < i1; i++) {
        int g = batch[i];
        float v = g_h[(size_t)i * H + j];
        if (g != curG) {
            atomicAdd(&g_hp[curG * H + j], acc);
            if (j == 0) atomicAdd(&g_cntg[curG], (float)run);
            acc = 0.f; run = 0; curG = g;
        }
        acc += v; run++;
    }
    atomicAdd(&g_hp[curG * H + j], acc);
    if (j == 0) atomicAdd(&g_cntg[curG], (float)run);
}

__global__ void k_out(const float* __restrict__ W,
                      const float* __restrict__ b,
                      float* __restrict__ out) {
    int g = blockIdx.x;
    int j = threadIdx.x;
    const float* hp = g_hp + g * H;
    float acc = g_cntg[g] * b[j];
#pragma unroll 8
    for (int k = 0; k < H; k++)
        acc = fmaf(hp[k], W[k * OUT_F + j], acc);
    out[g * OUT_F + j] = acc;
}

extern "C" void kernel_launch(void* const* d_in, const int* in_sizes, int n_in,
                              void* d_out, int out_size) {
    const float* x      = (const float*)d_in[0];
    const int*   ei     = (const int*)  d_in[1];
    const float* attr   = (const float*)d_in[2];
    const int*   batch  = (const int*)  d_in[3];
    const float* emb_W  = (const float*)d_in[4];
    const float* emb_b  = (const float*)d_in[5];
    const float* edge_W = (const float*)d_in[6];
    const float* edge_b = (const float*)d_in[7];
    const float* nn_W   = (const float*)d_in[8];
    const float* nn_b   = (const float*)d_in[9];
    const float* bn_g   = (const float*)d_in[10];
    const float* bn_b   = (const float*)d_in[11];
    const float* lin_W  = (const float*)d_in[12];
    const float* lin_b  = (const float*)d_in[13];
    float* out = (float*)d_out;

    cudaFuncSetAttribute(k_nodegemm,
                         cudaFuncAttributeMaxDynamicSharedMemorySize,
                         H * H * (int)sizeof(float));

    const int ew_grid = (N_NODES * H / 4 + 255) / 256;
    const int eg      = (N_EDGES + 255) / 256;
    const int mega    = MEGA_EMBED_BLKS + MEGA_HIST_BLKS + MEGA_ZERO_BLKS;
    const int ggrid   = N_EDGES / CHUNK;                  // 6250 blocks

    k_megainit<<<mega, 128>>>(x, emb_W, emb_b, ei);      // my launch 0
    k_scanfused<<<SCAN_NBLK, SCAN_CHUNK>>>();             // 1
    k_fill<<<eg, 256>>>(ei, attr);                        // 2
    for (int l = 0; l < NLAYERS; l++) {
        k_gatheragg<<<ggrid, 256>>>(                      // 3 -> ncu global #5
            edge_W + (size_t)l * E_FEAT * H, edge_b + (size_t)l * H);
        k_nodegemm<<<296, 256, H * H * sizeof(float)>>>(
            nn_W + (size_t)l * H * H, nn_b + (size_t)l * H);
        k_bnstats<<<1, H>>>();
        k_apply<<<ew_grid, 256>>>(bn_g + (size_t)l * H, bn_b + (size_t)l * H);
    }
    k_pool<<<1024, 128>>>(batch);
    k_out<<<NG, OUT_F>>>(lin_W, lin_b, out);
}